// round 2
// baseline (speedup 1.0000x reference)
#include <cuda_runtime.h>
#include <math.h>

// ---------------- problem constants ----------------
#define Bb   16
#define Cc   128
#define Nn   1024
#define Ll   12
#define Hh   8
#define DKk  16
#define NL   12288          // Nn*Ll
#define HLt  96             // Hh*Ll

#define X_SZ   25165824     // B*C*N*L
#define WB_SZ  1572864      // C*N*L
#define AP_SZ  1048576      // N*N
#define AH_SZ  16777216     // B*N*N

#define X_OFF   0
#define W_OFF   25165824
#define B_OFF   26738688
#define AP_OFF  28311552
#define AH_OFF  29360128
#define AF_OFF  46137344

// ---------------- scratch (static device globals; no allocs) ----------------
__device__ float g_SA[X_SZ];
__device__ float g_SB[X_SZ];
__device__ float g_SC[X_SZ];
__device__ float g_K[HLt * Nn * DKk];          // softmaxed memory
__device__ float g_KV[Bb * HLt * DKk * DKk];   // kv per (b,h,l)
__device__ float g_gate[3 * Bb * Cc];          // SE gates: q, v, c

// =====================================================================
// 1x1 conv (per-b GEMM 128x128x12288) + bias + ReLU.  Y[b][o][m]
// 128x128 output tile per block, 256 threads, 8x8 register tile, K-chunk 32.
// =====================================================================
__global__ __launch_bounds__(256) void conv_relu_kernel(
    const float* __restrict__ X, const float* __restrict__ W,
    const float* __restrict__ bias, float* __restrict__ Y)
{
    __shared__ float Ws[32][132];   // Ws[k][o]  (transposed W chunk)
    __shared__ float Xs[32][132];   // Xs[k][m]
    const int b  = blockIdx.y;
    const int m0 = blockIdx.x * 128;
    const int tid = threadIdx.x;
    const int ty = tid >> 4, tx = tid & 15;

    float acc[8][8];
#pragma unroll
    for (int i = 0; i < 8; i++)
#pragma unroll
        for (int j = 0; j < 8; j++) acc[i][j] = 0.f;

    const float* Xb = X + (size_t)b * Cc * NL;

    for (int k0 = 0; k0 < Cc; k0 += 32) {
#pragma unroll
        for (int it = 0; it < 16; it++) {           // 4096 elems: W chunk (transpose)
            int idx = tid + it * 256;
            int k = idx & 31, o = idx >> 5;
            Ws[k][o] = W[o * Cc + k0 + k];
        }
#pragma unroll
        for (int it = 0; it < 16; it++) {           // 4096 elems: X chunk
            int idx = tid + it * 256;
            int m = idx & 127, k = idx >> 7;
            Xs[k][m] = Xb[(size_t)(k0 + k) * NL + m0 + m];
        }
        __syncthreads();
#pragma unroll
        for (int k = 0; k < 32; k++) {
            float a[8], bv[8];
            *(float4*)&a[0]  = *(const float4*)&Ws[k][ty * 8];
            *(float4*)&a[4]  = *(const float4*)&Ws[k][ty * 8 + 4];
            *(float4*)&bv[0] = *(const float4*)&Xs[k][tx * 8];
            *(float4*)&bv[4] = *(const float4*)&Xs[k][tx * 8 + 4];
#pragma unroll
            for (int i = 0; i < 8; i++)
#pragma unroll
                for (int j = 0; j < 8; j++) acc[i][j] += a[i] * bv[j];
        }
        __syncthreads();
    }

    float* Yb = Y + (size_t)b * Cc * NL;
#pragma unroll
    for (int i = 0; i < 8; i++) {
        const int o = ty * 8 + i;
        const float bo = bias[o];
#pragma unroll
        for (int j = 0; j < 8; j++) {
            float v = acc[i][j] + bo;
            Yb[(size_t)o * NL + m0 + tx * 8 + j] = v > 0.f ? v : 0.f;
        }
    }
}

// =====================================================================
// Global-avg-pool over (n,l) + SE MLP -> sigmoid gate per (b,c).
// One block per b; one warp per channel stripe.
// =====================================================================
__global__ __launch_bounds__(256) void pool_se_kernel(
    const float* __restrict__ Y, const float* __restrict__ f1,
    const float* __restrict__ f2, float* __restrict__ gate)
{
    __shared__ float means[Cc];
    __shared__ float h1[8];
    const int b = blockIdx.x;
    const int tid = threadIdx.x, lane = tid & 31, wid = tid >> 5;

    for (int c = wid; c < Cc; c += 8) {
        const float4* row = (const float4*)(Y + ((size_t)b * Cc + c) * NL);
        float s = 0.f;
        for (int i = lane; i < NL / 4; i += 32) {
            float4 v = row[i];
            s += (v.x + v.y) + (v.z + v.w);
        }
#pragma unroll
        for (int o = 16; o > 0; o >>= 1) s += __shfl_xor_sync(0xffffffffu, s, o);
        if (lane == 0) means[c] = s * (1.f / (float)NL);
    }
    __syncthreads();
    if (tid < 8) {
        float s = 0.f;
        for (int c = 0; c < Cc; c++) s += f1[tid * Cc + c] * means[c];
        h1[tid] = s > 0.f ? s : 0.f;
    }
    __syncthreads();
    if (tid < Cc) {
        float s = 0.f;
#pragma unroll
        for (int j = 0; j < 8; j++) s += f2[tid * 8 + j] * h1[j];
        gate[b * Cc + tid] = 1.f / (1.f + expf(-s));
    }
}

// =====================================================================
// q branch: gate, *scale, softmax over DK, transpose to [B,H,L,N,DK]
// =====================================================================
__global__ __launch_bounds__(256) void softmax_q_kernel(
    const float* __restrict__ Y, const float* __restrict__ gate,
    float* __restrict__ QS)
{
    const int t = blockIdx.x * 256 + threadIdx.x;   // over B*H*NL
    const int nl = t % NL;
    const int bh = t / NL;
    const int h = bh & 7, b = bh >> 3;
    const int n = nl / Ll, l = nl % Ll;
    const float scale = 0.25f;

    float v[16]; float mx = -1e30f;
#pragma unroll
    for (int d = 0; d < 16; d++) {
        const int c = h * 16 + d;
        float val = Y[((size_t)b * Cc + c) * NL + nl] * gate[b * Cc + c] * scale;
        v[d] = val; mx = fmaxf(mx, val);
    }
    float s = 0.f;
#pragma unroll
    for (int d = 0; d < 16; d++) { v[d] = expf(v[d] - mx); s += v[d]; }
    const float inv = 1.f / s;
#pragma unroll
    for (int d = 0; d < 16; d++) v[d] *= inv;
    float4* out = (float4*)&QS[(((size_t)(b * Hh + h) * Ll + l) * Nn + n) * 16];
    out[0] = *(float4*)&v[0];  out[1] = *(float4*)&v[4];
    out[2] = *(float4*)&v[8];  out[3] = *(float4*)&v[12];
}

// v branch: gate + transpose to [B,H,L,N,DK]
__global__ __launch_bounds__(256) void trans_v_kernel(
    const float* __restrict__ Y, const float* __restrict__ gate,
    float* __restrict__ VT)
{
    const int t = blockIdx.x * 256 + threadIdx.x;
    const int nl = t % NL;
    const int bh = t / NL;
    const int h = bh & 7, b = bh >> 3;
    const int n = nl / Ll, l = nl % Ll;

    float v[16];
#pragma unroll
    for (int d = 0; d < 16; d++) {
        const int c = h * 16 + d;
        v[d] = Y[((size_t)b * Cc + c) * NL + nl] * gate[b * Cc + c];
    }
    float4* out = (float4*)&VT[(((size_t)(b * Hh + h) * Ll + l) * Nn + n) * 16];
    out[0] = *(float4*)&v[0];  out[1] = *(float4*)&v[4];
    out[2] = *(float4*)&v[8];  out[3] = *(float4*)&v[12];
}

// k = softmax(memory * scale, axis=-1)
__global__ __launch_bounds__(256) void ksoft_kernel(
    const float* __restrict__ mem, float* __restrict__ K)
{
    const int t = blockIdx.x * 256 + threadIdx.x;   // over HL*N
    const float scale = 0.25f;
    float v[16]; float mx = -1e30f;
    const float4* p = (const float4*)(mem + (size_t)t * 16);
    float4 r[4] = {p[0], p[1], p[2], p[3]};
#pragma unroll
    for (int q = 0; q < 4; q++) {
        v[q*4+0] = r[q].x * scale; v[q*4+1] = r[q].y * scale;
        v[q*4+2] = r[q].z * scale; v[q*4+3] = r[q].w * scale;
    }
#pragma unroll
    for (int d = 0; d < 16; d++) mx = fmaxf(mx, v[d]);
    float s = 0.f;
#pragma unroll
    for (int d = 0; d < 16; d++) { v[d] = expf(v[d] - mx); s += v[d]; }
    const float inv = 1.f / s;
#pragma unroll
    for (int d = 0; d < 16; d++) v[d] *= inv;
    float4* out = (float4*)(K + (size_t)t * 16);
    out[0] = *(float4*)&v[0];  out[1] = *(float4*)&v[4];
    out[2] = *(float4*)&v[8];  out[3] = *(float4*)&v[12];
}

// A_p = softmax(relu(nv1 @ nv2), axis=-1), one block per row n
__global__ __launch_bounds__(256) void ap_kernel(
    const float* __restrict__ nv1, const float* __restrict__ nv2,
    float* __restrict__ AP)
{
    const int n = blockIdx.x, tid = threadIdx.x, lane = tid & 31, wid = tid >> 5;
    __shared__ float red[8];
    __shared__ float bval;
    float a[10];
#pragma unroll
    for (int t = 0; t < 10; t++) a[t] = nv1[n * 10 + t];
    float v[4];
#pragma unroll
    for (int j = 0; j < 4; j++) {
        const int m = tid + j * 256;
        float s = 0.f;
#pragma unroll
        for (int t = 0; t < 10; t++) s += a[t] * nv2[t * Nn + m];
        v[j] = s > 0.f ? s : 0.f;
    }
    float mx = fmaxf(fmaxf(v[0], v[1]), fmaxf(v[2], v[3]));
#pragma unroll
    for (int o = 16; o > 0; o >>= 1) mx = fmaxf(mx, __shfl_xor_sync(0xffffffffu, mx, o));
    if (lane == 0) red[wid] = mx;
    __syncthreads();
    if (tid == 0) { float t = red[0]; for (int w = 1; w < 8; w++) t = fmaxf(t, red[w]); bval = t; }
    __syncthreads();
    mx = bval;
    float s = 0.f;
#pragma unroll
    for (int j = 0; j < 4; j++) { v[j] = expf(v[j] - mx); s += v[j]; }
#pragma unroll
    for (int o = 16; o > 0; o >>= 1) s += __shfl_xor_sync(0xffffffffu, s, o);
    if (lane == 0) red[wid] = s;
    __syncthreads();
    if (tid == 0) { float t = 0.f; for (int w = 0; w < 8; w++) t += red[w]; bval = t; }
    __syncthreads();
    const float inv = 1.f / bval;
#pragma unroll
    for (int j = 0; j < 4; j++) AP[(size_t)n * Nn + tid + j * 256] = v[j] * inv;
}

// =====================================================================
// A_h[b][n][m] = (1/8) * sum_{hl,c} QS[b][hl][n][c] * K[hl][m][c]
// 128x128 tile per block; K chunked by hl slab (16).
// =====================================================================
__global__ __launch_bounds__(256) void ah_gemm_kernel(
    const float* __restrict__ QS, const float* __restrict__ K,
    float* __restrict__ AH)
{
    __shared__ float As[16][132];   // As[c][n]
    __shared__ float Bs[16][132];   // Bs[c][m]
    const int b  = blockIdx.z;
    const int n0 = blockIdx.y * 128;
    const int m0 = blockIdx.x * 128;
    const int tid = threadIdx.x;
    const int ty = tid >> 4, tx = tid & 15;

    float acc[8][8];
#pragma unroll
    for (int i = 0; i < 8; i++)
#pragma unroll
        for (int j = 0; j < 8; j++) acc[i][j] = 0.f;

    const float* Qb = QS + (size_t)b * HLt * Nn * DKk;

    for (int hl = 0; hl < HLt; hl++) {
        const float* qsl = Qb + (size_t)hl * Nn * DKk + (size_t)n0 * 16;
        const float* ksl = K  + (size_t)hl * Nn * DKk + (size_t)m0 * 16;
#pragma unroll
        for (int it = 0; it < 8; it++) {    // 2048 contiguous floats each
            int idx = tid + it * 256;
            int d = idx & 15, nn = idx >> 4;
            As[d][nn] = qsl[idx];
            Bs[d][nn] = ksl[idx];
        }
        __syncthreads();
#pragma unroll
        for (int k = 0; k < 16; k++) {
            float a[8], bv[8];
            *(float4*)&a[0]  = *(const float4*)&As[k][ty * 8];
            *(float4*)&a[4]  = *(const float4*)&As[k][ty * 8 + 4];
            *(float4*)&bv[0] = *(const float4*)&Bs[k][tx * 8];
            *(float4*)&bv[4] = *(const float4*)&Bs[k][tx * 8 + 4];
#pragma unroll
            for (int i = 0; i < 8; i++)
#pragma unroll
                for (int j = 0; j < 8; j++) acc[i][j] += a[i] * bv[j];
        }
        __syncthreads();
    }

    float* Ab = AH + (size_t)b * Nn * Nn;
#pragma unroll
    for (int i = 0; i < 8; i++) {
        const int n = n0 + ty * 8 + i;
#pragma unroll
        for (int j = 0; j < 8; j++)
            Ab[(size_t)n * Nn + m0 + tx * 8 + j] = acc[i][j] * 0.125f;
    }
}

// kv[b][hl][x][y] = sum_n K[hl][n][x] * VT[b][hl][n][y]
__global__ __launch_bounds__(256) void kv_kernel(
    const float* __restrict__ K, const float* __restrict__ VT,
    float* __restrict__ KV)
{
    const int hl = blockIdx.x, b = blockIdx.y;
    __shared__ float ks[128][16];
    __shared__ float vs[128][16];
    const int tid = threadIdx.x;
    const int x = tid >> 4, y = tid & 15;
    float acc = 0.f;
    const float* kb = K  + (size_t)hl * Nn * 16;
    const float* vb = VT + ((size_t)b * HLt + hl) * Nn * 16;
    for (int n0 = 0; n0 < Nn; n0 += 128) {
#pragma unroll
        for (int it = 0; it < 8; it++) {
            int idx = tid + it * 256;
            int d = idx & 15, nn = idx >> 4;
            ks[nn][d] = kb[(size_t)n0 * 16 + idx];
            vs[nn][d] = vb[(size_t)n0 * 16 + idx];
        }
        __syncthreads();
#pragma unroll
        for (int nn = 0; nn < 128; nn++) acc += ks[nn][x] * vs[nn][y];
        __syncthreads();
    }
    KV[((size_t)b * HLt + hl) * 256 + tid] = acc;
}

// x5[b][h*16+y][n][l] = sum_x QS[b,h,l,n,x]*kv[b,h,l,x,y] + VT[b,h,l,n,y]
// block = (32 n) x (12 l) = 384 threads
__global__ __launch_bounds__(384) void attn_kernel(
    const float* __restrict__ QS, const float* __restrict__ VT,
    const float* __restrict__ KV, float* __restrict__ XO)
{
    const int n0 = blockIdx.x * 32, h = blockIdx.y, b = blockIdx.z;
    __shared__ float kvs[16 * 16 * Ll];   // [x][y][l]
    const int tid = threadIdx.x;
    for (int idx = tid; idx < 16 * 16 * Ll; idx += 384) {
        const int l = idx % Ll, xy = idx / Ll;
        kvs[idx] = KV[((size_t)b * HLt + h * Ll + l) * 256 + xy];
    }
    __syncthreads();
    const int nloc = tid / Ll, l = tid % Ll;
    const int n = n0 + nloc;
    const float* qp = &QS[(((size_t)(b * Hh + h) * Ll + l) * Nn + n) * 16];
    const float* vp = &VT[(((size_t)(b * Hh + h) * Ll + l) * Nn + n) * 16];
    float q[16], o[16];
    *(float4*)&q[0]  = ((const float4*)qp)[0]; *(float4*)&q[4]  = ((const float4*)qp)[1];
    *(float4*)&q[8]  = ((const float4*)qp)[2]; *(float4*)&q[12] = ((const float4*)qp)[3];
    *(float4*)&o[0]  = ((const float4*)vp)[0]; *(float4*)&o[4]  = ((const float4*)vp)[1];
    *(float4*)&o[8]  = ((const float4*)vp)[2]; *(float4*)&o[12] = ((const float4*)vp)[3];
#pragma unroll
    for (int x = 0; x < 16; x++) {
        const float qx = q[x];
#pragma unroll
        for (int y = 0; y < 16; y++) o[y] += qx * kvs[(x * 16 + y) * Ll + l];
    }
    float* xb = XO + (size_t)b * Cc * NL;
#pragma unroll
    for (int y = 0; y < 16; y++)
        xb[(size_t)(h * 16 + y) * NL + n * Ll + l] = o[y];
}

// out_x = (Y*gate) * (weight+1) + bias
__global__ __launch_bounds__(256) void final_kernel(
    const float* __restrict__ Y, const float* __restrict__ gate,
    const float* __restrict__ wgt, const float* __restrict__ bias,
    float* __restrict__ OX)
{
    const size_t i4 = (size_t)blockIdx.x * 256 + threadIdx.x;  // over X_SZ/4
    if (i4 >= X_SZ / 4) return;
    const size_t rest4 = i4 % (Cc * NL / 4);
    const int b = (int)(i4 / (Cc * NL / 4));
    const int c = (int)(rest4 / (NL / 4));
    const float g = gate[b * Cc + c];
    float4 y = ((const float4*)Y)[i4];
    float4 w = ((const float4*)wgt)[rest4];
    float4 bi = ((const float4*)bias)[rest4];
    float4 r;
    r.x = y.x * g * (w.x + 1.f) + bi.x;
    r.y = y.y * g * (w.y + 1.f) + bi.y;
    r.z = y.z * g * (w.z + 1.f) + bi.z;
    r.w = y.w * g * (w.w + 1.f) + bi.w;
    ((float4*)OX)[i4] = r;
}

// A_f = A_h + A_p (broadcast over b)
__global__ __launch_bounds__(256) void af_kernel(float* __restrict__ out)
{
    const size_t i = (size_t)blockIdx.x * 256 + threadIdx.x;   // over AH_SZ/4
    const float4* ah = (const float4*)(out + AH_OFF);
    const float4* ap = (const float4*)(out + AP_OFF);
    float4* af = (float4*)(out + AF_OFF);
    float4 a = ah[i];
    float4 p = ap[i & (AP_SZ / 4 - 1)];
    float4 r = {a.x + p.x, a.y + p.y, a.z + p.z, a.w + p.w};
    af[i] = r;
}

// =====================================================================
extern "C" void kernel_launch(void* const* d_in, const int* in_sizes, int n_in,
                              void* d_out, int out_size)
{
    (void)in_sizes; (void)n_in; (void)out_size;
    const float* x    = (const float*)d_in[0];
    const float* Wq   = (const float*)d_in[1];
    const float* bq   = (const float*)d_in[2];
    const float* fq1  = (const float*)d_in[3];
    const float* fq2  = (const float*)d_in[4];
    const float* Wv   = (const float*)d_in[5];
    const float* bv   = (const float*)d_in[6];
    const float* fv1  = (const float*)d_in[7];
    const float* fv2  = (const float*)d_in[8];
    const float* Wc   = (const float*)d_in[9];
    const float* bc   = (const float*)d_in[10];
    const float* fc1  = (const float*)d_in[11];
    const float* fc2  = (const float*)d_in[12];
    const float* mem  = (const float*)d_in[13];
    const float* wgt  = (const float*)d_in[14];
    const float* bia  = (const float*)d_in[15];
    const float* nv1  = (const float*)d_in[16];
    const float* nv2  = (const float*)d_in[17];
    float* out = (float*)d_out;

    float *SA, *SB, *SC, *GK, *GKV, *GATE;
    cudaGetSymbolAddress((void**)&SA,   g_SA);
    cudaGetSymbolAddress((void**)&SB,   g_SB);
    cudaGetSymbolAddress((void**)&SC,   g_SC);
    cudaGetSymbolAddress((void**)&GK,   g_K);
    cudaGetSymbolAddress((void**)&GKV,  g_KV);
    cudaGetSymbolAddress((void**)&GATE, g_gate);
    float* gate_q = GATE;
    float* gate_v = GATE + Bb * Cc;
    float* gate_c = GATE + 2 * Bb * Cc;

    const dim3 convGrid(NL / 128, Bb);

    // q and v conv branches
    conv_relu_kernel<<<convGrid, 256>>>(x, Wq, bq, SA);
    conv_relu_kernel<<<convGrid, 256>>>(x, Wv, bv, SB);
    pool_se_kernel<<<Bb, 256>>>(SA, fq1, fq2, gate_q);
    pool_se_kernel<<<Bb, 256>>>(SB, fv1, fv2, gate_v);

    // qs (softmaxed, transposed) and gated v (transposed)
    softmax_q_kernel<<<(Bb * Hh * NL) / 256, 256>>>(SA, gate_q, SC);
    trans_v_kernel<<<(Bb * Hh * NL) / 256, 256>>>(SB, gate_v, SA);

    // k softmax and A_p
    ksoft_kernel<<<(HLt * Nn) / 256, 256>>>(mem, GK);
    ap_kernel<<<Nn, 256>>>(nv1, nv2, out + AP_OFF);

    // A_h (dominant GEMM)
    ah_gemm_kernel<<<dim3(8, 8, Bb), 256>>>(SC, GK, out + AH_OFF);

    // kv then attention output (attn_dyn == v since A_p rows sum to 1)
    kv_kernel<<<dim3(HLt, Bb), 256>>>(GK, SA, GKV);
    attn_kernel<<<dim3(Nn / 32, Hh, Bb), 384>>>(SC, SA, GKV, SB);

    // output conv branch + SE + final affine
    conv_relu_kernel<<<convGrid, 256>>>(SB, Wc, bc, SC);
    pool_se_kernel<<<Bb, 256>>>(SC, fc1, fc2, gate_c);
    final_kernel<<<(X_SZ / 4 + 255) / 256, 256>>>(SC, gate_c, wgt, bia, out + X_OFF);

    // passthrough outputs + A_f
    cudaMemcpyAsync(out + W_OFF, wgt, (size_t)WB_SZ * sizeof(float),
                    cudaMemcpyDeviceToDevice, 0);
    cudaMemcpyAsync(out + B_OFF, bia, (size_t)WB_SZ * sizeof(float),
                    cudaMemcpyDeviceToDevice, 0);
    af_kernel<<<AH_SZ / 4 / 256, 256>>>(out);
}

// round 4
// speedup vs baseline: 3.1043x; 3.1043x over previous
#include <cuda_runtime.h>
#include <cuda_bf16.h>
#include <math.h>
#include <stdint.h>

// ---------------- problem constants ----------------
#define Bb   16
#define Cc   128
#define Nn   1024
#define Ll   12
#define Hh   8
#define DKk  16
#define NL   12288          // Nn*Ll
#define HLt  96             // Hh*Ll

#define X_SZ   25165824     // B*C*N*L
#define WB_SZ  1572864      // C*N*L
#define AP_SZ  1048576      // N*N
#define AH_SZ  16777216     // B*N*N

#define X_OFF   0
#define W_OFF   25165824
#define B_OFF   26738688
#define AP_OFF  28311552
#define AH_OFF  29360128
#define AF_OFF  46137344

// ---------------- scratch (static device globals; no allocs) ----------------
__device__ float g_SA[X_SZ];
__device__ float g_SB[X_SZ];
__device__ float g_SC[X_SZ];
__device__ float g_K[HLt * Nn * DKk];            // softmaxed memory (fp32, for kv)
__device__ float g_KV[Bb * HLt * DKk * DKk];     // kv per (b,h,l)
__device__ float g_gate[3 * Bb * Cc];            // SE gates: q, v, c
__device__ float g_psum[3 * Bb * 96 * Cc];       // per-conv-block partial sums
__device__ __nv_bfloat16 g_Qh[(size_t)Bb * HLt * Nn * DKk];  // bf16 qs for MMA
__device__ __nv_bfloat16 g_Kh[HLt * Nn * DKk];               // bf16 k for MMA

// =====================================================================
// 1x1 conv (per-b GEMM 128x128x12288) + bias + ReLU + per-block pool partials.
// =====================================================================
__global__ __launch_bounds__(256) void conv_relu_kernel(
    const float* __restrict__ X, const float* __restrict__ W,
    const float* __restrict__ bias, float* __restrict__ Y,
    float* __restrict__ psum)
{
    __shared__ float Ws[32][132];   // Ws[k][o]
    __shared__ float Xs[32][132];   // Xs[k][m]
    const int b  = blockIdx.y;
    const int mblk = blockIdx.x;
    const int m0 = mblk * 128;
    const int tid = threadIdx.x;
    const int ty = tid >> 4, tx = tid & 15;

    float acc[8][8];
#pragma unroll
    for (int i = 0; i < 8; i++)
#pragma unroll
        for (int j = 0; j < 8; j++) acc[i][j] = 0.f;

    const float* Xb = X + (size_t)b * Cc * NL;

    for (int k0 = 0; k0 < Cc; k0 += 32) {
#pragma unroll
        for (int it = 0; it < 16; it++) {
            int idx = tid + it * 256;
            int k = idx & 31, o = idx >> 5;
            Ws[k][o] = W[o * Cc + k0 + k];
        }
#pragma unroll
        for (int it = 0; it < 16; it++) {
            int idx = tid + it * 256;
            int m = idx & 127, k = idx >> 7;
            Xs[k][m] = Xb[(size_t)(k0 + k) * NL + m0 + m];
        }
        __syncthreads();
#pragma unroll
        for (int k = 0; k < 32; k++) {
            float a[8], bv[8];
            *(float4*)&a[0]  = *(const float4*)&Ws[k][ty * 8];
            *(float4*)&a[4]  = *(const float4*)&Ws[k][ty * 8 + 4];
            *(float4*)&bv[0] = *(const float4*)&Xs[k][tx * 8];
            *(float4*)&bv[4] = *(const float4*)&Xs[k][tx * 8 + 4];
#pragma unroll
            for (int i = 0; i < 8; i++)
#pragma unroll
                for (int j = 0; j < 8; j++) acc[i][j] += a[i] * bv[j];
        }
        __syncthreads();
    }

    float* Yb = Y + (size_t)b * Cc * NL;
    float csum[8];
#pragma unroll
    for (int i = 0; i < 8; i++) {
        const int o = ty * 8 + i;
        const float bo = bias[o];
        float s = 0.f;
#pragma unroll
        for (int j = 0; j < 8; j++) {
            float v = acc[i][j] + bo;
            v = v > 0.f ? v : 0.f;
            Yb[(size_t)o * NL + m0 + tx * 8 + j] = v;
            s += v;
        }
        csum[i] = s;
    }
#pragma unroll
    for (int i = 0; i < 8; i++) {
#pragma unroll
        for (int off = 8; off > 0; off >>= 1)
            csum[i] += __shfl_down_sync(0xffffffffu, csum[i], off);
    }
    if (tx == 0) {
        float* pp = psum + ((size_t)(b * 96 + mblk)) * Cc + ty * 8;
#pragma unroll
        for (int i = 0; i < 8; i++) pp[i] = csum[i];
    }
}

// tiny SE: reduce 96 partials per (b,c), MLP, sigmoid gate
__global__ __launch_bounds__(128) void se_kernel(
    const float* __restrict__ psum, const float* __restrict__ f1,
    const float* __restrict__ f2, float* __restrict__ gate)
{
    __shared__ float means[Cc];
    __shared__ float h1[8];
    const int b = blockIdx.x, tid = threadIdx.x;
    float s = 0.f;
    for (int m = 0; m < 96; m++)
        s += psum[((size_t)(b * 96 + m)) * Cc + tid];
    means[tid] = s * (1.f / (float)NL);
    __syncthreads();
    if (tid < 8) {
        float t = 0.f;
        for (int c = 0; c < Cc; c++) t += f1[tid * Cc + c] * means[c];
        h1[tid] = t > 0.f ? t : 0.f;
    }
    __syncthreads();
    float t = 0.f;
#pragma unroll
    for (int j = 0; j < 8; j++) t += f2[tid * 8 + j] * h1[j];
    gate[b * Cc + tid] = 1.f / (1.f + expf(-t));
}

// =====================================================================
// q branch: gate, *scale, softmax over DK, transpose -> fp32 QS + bf16 QSh
// =====================================================================
__global__ __launch_bounds__(256) void softmax_q_kernel(
    const float* __restrict__ Y, const float* __restrict__ gate,
    float* __restrict__ QS, __nv_bfloat16* __restrict__ QSh)
{
    const int t = blockIdx.x * 256 + threadIdx.x;
    const int nl = t % NL;
    const int bh = t / NL;
    const int h = bh & 7, b = bh >> 3;
    const int n = nl / Ll, l = nl % Ll;
    const float scale = 0.25f;

    float v[16]; float mx = -1e30f;
#pragma unroll
    for (int d = 0; d < 16; d++) {
        const int c = h * 16 + d;
        float val = Y[((size_t)b * Cc + c) * NL + nl] * gate[b * Cc + c] * scale;
        v[d] = val; mx = fmaxf(mx, val);
    }
    float s = 0.f;
#pragma unroll
    for (int d = 0; d < 16; d++) { v[d] = expf(v[d] - mx); s += v[d]; }
    const float inv = 1.f / s;
#pragma unroll
    for (int d = 0; d < 16; d++) v[d] *= inv;
    const size_t base = (((size_t)(b * Hh + h) * Ll + l) * Nn + n) * 16;
    float4* out = (float4*)&QS[base];
    out[0] = *(float4*)&v[0];  out[1] = *(float4*)&v[4];
    out[2] = *(float4*)&v[8];  out[3] = *(float4*)&v[12];
    __nv_bfloat162 hb[8];
#pragma unroll
    for (int d = 0; d < 8; d++) hb[d] = __floats2bfloat162_rn(v[2*d], v[2*d+1]);
    uint4* outh = (uint4*)&QSh[base];
    outh[0] = *(uint4*)&hb[0];
    outh[1] = *(uint4*)&hb[4];
}

// v branch: gate + transpose to [B,H,L,N,DK]
__global__ __launch_bounds__(256) void trans_v_kernel(
    const float* __restrict__ Y, const float* __restrict__ gate,
    float* __restrict__ VT)
{
    const int t = blockIdx.x * 256 + threadIdx.x;
    const int nl = t % NL;
    const int bh = t / NL;
    const int h = bh & 7, b = bh >> 3;
    const int n = nl / Ll, l = nl % Ll;

    float v[16];
#pragma unroll
    for (int d = 0; d < 16; d++) {
        const int c = h * 16 + d;
        v[d] = Y[((size_t)b * Cc + c) * NL + nl] * gate[b * Cc + c];
    }
    float4* out = (float4*)&VT[(((size_t)(b * Hh + h) * Ll + l) * Nn + n) * 16];
    out[0] = *(float4*)&v[0];  out[1] = *(float4*)&v[4];
    out[2] = *(float4*)&v[8];  out[3] = *(float4*)&v[12];
}

// k = softmax(memory * scale, axis=-1) -> fp32 + bf16
__global__ __launch_bounds__(256) void ksoft_kernel(
    const float* __restrict__ mem, float* __restrict__ K,
    __nv_bfloat16* __restrict__ Kh)
{
    const int t = blockIdx.x * 256 + threadIdx.x;
    const float scale = 0.25f;
    float v[16]; float mx = -1e30f;
    const float4* p = (const float4*)(mem + (size_t)t * 16);
    float4 r[4] = {p[0], p[1], p[2], p[3]};
#pragma unroll
    for (int q = 0; q < 4; q++) {
        v[q*4+0] = r[q].x * scale; v[q*4+1] = r[q].y * scale;
        v[q*4+2] = r[q].z * scale; v[q*4+3] = r[q].w * scale;
    }
#pragma unroll
    for (int d = 0; d < 16; d++) mx = fmaxf(mx, v[d]);
    float s = 0.f;
#pragma unroll
    for (int d = 0; d < 16; d++) { v[d] = expf(v[d] - mx); s += v[d]; }
    const float inv = 1.f / s;
#pragma unroll
    for (int d = 0; d < 16; d++) v[d] *= inv;
    float4* out = (float4*)(K + (size_t)t * 16);
    out[0] = *(float4*)&v[0];  out[1] = *(float4*)&v[4];
    out[2] = *(float4*)&v[8];  out[3] = *(float4*)&v[12];
    __nv_bfloat162 hb[8];
#pragma unroll
    for (int d = 0; d < 8; d++) hb[d] = __floats2bfloat162_rn(v[2*d], v[2*d+1]);
    uint4* outh = (uint4*)&Kh[(size_t)t * 16];
    outh[0] = *(uint4*)&hb[0];
    outh[1] = *(uint4*)&hb[4];
}

// A_p = softmax(relu(nv1 @ nv2), axis=-1), one block per row n
__global__ __launch_bounds__(256) void ap_kernel(
    const float* __restrict__ nv1, const float* __restrict__ nv2,
    float* __restrict__ AP)
{
    const int n = blockIdx.x, tid = threadIdx.x, lane = tid & 31, wid = tid >> 5;
    __shared__ float red[8];
    __shared__ float bval;
    float a[10];
#pragma unroll
    for (int t = 0; t < 10; t++) a[t] = nv1[n * 10 + t];
    float v[4];
#pragma unroll
    for (int j = 0; j < 4; j++) {
        const int m = tid + j * 256;
        float s = 0.f;
#pragma unroll
        for (int t = 0; t < 10; t++) s += a[t] * nv2[t * Nn + m];
        v[j] = s > 0.f ? s : 0.f;
    }
    float mx = fmaxf(fmaxf(v[0], v[1]), fmaxf(v[2], v[3]));
#pragma unroll
    for (int o = 16; o > 0; o >>= 1) mx = fmaxf(mx, __shfl_xor_sync(0xffffffffu, mx, o));
    if (lane == 0) red[wid] = mx;
    __syncthreads();
    if (tid == 0) { float t = red[0]; for (int w = 1; w < 8; w++) t = fmaxf(t, red[w]); bval = t; }
    __syncthreads();
    mx = bval;
    float s = 0.f;
#pragma unroll
    for (int j = 0; j < 4; j++) { v[j] = expf(v[j] - mx); s += v[j]; }
#pragma unroll
    for (int o = 16; o > 0; o >>= 1) s += __shfl_xor_sync(0xffffffffu, s, o);
    if (lane == 0) red[wid] = s;
    __syncthreads();
    if (tid == 0) { float t = 0.f; for (int w = 0; w < 8; w++) t += red[w]; bval = t; }
    __syncthreads();
    const float inv = 1.f / bval;
#pragma unroll
    for (int j = 0; j < 4; j++) AP[(size_t)n * Nn + tid + j * 256] = v[j] * inv;
}

// =====================================================================
// A_h via mma.sync (bf16 HMMA, fp32 accum):
// D[n][m] = (1/8) sum_{hl,c} QSh[b,hl,n,c] * Kh[hl,m,c]
// 128x128 tile per CTA, 8 warps (4x2), warp = 32 rows x 64 cols.
// K = 1536 chunked as 48 x 32 halves (2 hl-slabs). Smem stride 40 halves.
// =====================================================================
#define BKP 40
__global__ __launch_bounds__(256) void ah_mma_kernel(
    const __nv_bfloat16* __restrict__ Qh, const __nv_bfloat16* __restrict__ Kh,
    float* __restrict__ AH)
{
    __shared__ __nv_bfloat16 As[128 * BKP];
    __shared__ __nv_bfloat16 Bs[128 * BKP];
    const int b  = blockIdx.z;
    const int n0 = blockIdx.y * 128;
    const int m0 = blockIdx.x * 128;
    const int tid = threadIdx.x, wid = tid >> 5, lane = tid & 31;
    const int wm = wid & 3, wn = wid >> 2;
    const int gi = lane >> 2, tig = lane & 3;

    float c[2][8][4];
#pragma unroll
    for (int mi = 0; mi < 2; mi++)
#pragma unroll
        for (int ni = 0; ni < 8; ni++)
#pragma unroll
            for (int q = 0; q < 4; q++) c[mi][ni][q] = 0.f;

    const __nv_bfloat16* Qb = Qh + (size_t)b * HLt * Nn * DKk;
    const int lr = tid & 127;        // row loaded by this thread
    const int ls = tid >> 7;         // slab (0/1) within chunk

    for (int kc = 0; kc < 48; kc++) {
        const int hl0 = kc * 2;
        __syncthreads();
        {   // each thread loads one full 32B row-slab of A and of B
            const size_t gofs = ((size_t)(hl0 + ls) * Nn) * 16;
            const uint4* ga = (const uint4*)(Qb + gofs + (size_t)(n0 + lr) * 16);
            const uint4* gb = (const uint4*)(Kh + gofs + (size_t)(m0 + lr) * 16);
            uint4 a0 = ga[0], a1 = ga[1];
            uint4 b0 = gb[0], b1 = gb[1];
            __nv_bfloat16* pa = As + lr * BKP + ls * 16;
            __nv_bfloat16* pb = Bs + lr * BKP + ls * 16;
            *(uint4*)pa = a0; *(uint4*)(pa + 8) = a1;
            *(uint4*)pb = b0; *(uint4*)(pb + 8) = b1;
        }
        __syncthreads();
#pragma unroll
        for (int ks = 0; ks < 32; ks += 16) {
            uint32_t a[2][4];
#pragma unroll
            for (int mi = 0; mi < 2; mi++) {
                const __nv_bfloat16* ap =
                    As + (wm * 32 + mi * 16 + gi) * BKP + ks + tig * 2;
                a[mi][0] = *(const uint32_t*)ap;
                a[mi][1] = *(const uint32_t*)(ap + 8 * BKP);
                a[mi][2] = *(const uint32_t*)(ap + 8);
                a[mi][3] = *(const uint32_t*)(ap + 8 * BKP + 8);
            }
#pragma unroll
            for (int ni = 0; ni < 8; ni++) {
                const __nv_bfloat16* bp =
                    Bs + (wn * 64 + ni * 8 + gi) * BKP + ks + tig * 2;
                const uint32_t b0 = *(const uint32_t*)bp;
                const uint32_t b1 = *(const uint32_t*)(bp + 8);
#pragma unroll
                for (int mi = 0; mi < 2; mi++) {
                    asm volatile(
                        "mma.sync.aligned.m16n8k16.row.col.f32.bf16.bf16.f32 "
                        "{%0,%1,%2,%3}, {%4,%5,%6,%7}, {%8,%9}, {%0,%1,%2,%3};"
                        : "+f"(c[mi][ni][0]), "+f"(c[mi][ni][1]),
                          "+f"(c[mi][ni][2]), "+f"(c[mi][ni][3])
                        : "r"(a[mi][0]), "r"(a[mi][1]),
                          "r"(a[mi][2]), "r"(a[mi][3]),
                          "r"(b0), "r"(b1));
                }
            }
        }
    }

    float* Ab = AH + (size_t)b * Nn * Nn;
#pragma unroll
    for (int mi = 0; mi < 2; mi++) {
        const int r0 = n0 + wm * 32 + mi * 16 + gi;
#pragma unroll
        for (int ni = 0; ni < 8; ni++) {
            const int col = m0 + wn * 64 + ni * 8 + tig * 2;
            float2 v0 = {c[mi][ni][0] * 0.125f, c[mi][ni][1] * 0.125f};
            float2 v1 = {c[mi][ni][2] * 0.125f, c[mi][ni][3] * 0.125f};
            *(float2*)&Ab[(size_t)r0 * Nn + col] = v0;
            *(float2*)&Ab[(size_t)(r0 + 8) * Nn + col] = v1;
        }
    }
}

// kv[b][hl][x][y] = sum_n K[hl][n][x] * VT[b][hl][n][y]
__global__ __launch_bounds__(256) void kv_kernel(
    const float* __restrict__ K, const float* __restrict__ VT,
    float* __restrict__ KV)
{
    const int hl = blockIdx.x, b = blockIdx.y;
    __shared__ float ks[128][16];
    __shared__ float vs[128][16];
    const int tid = threadIdx.x;
    const int x = tid >> 4, y = tid & 15;
    float acc = 0.f;
    const float* kb = K  + (size_t)hl * Nn * 16;
    const float* vb = VT + ((size_t)b * HLt + hl) * Nn * 16;
    for (int n0 = 0; n0 < Nn; n0 += 128) {
#pragma unroll
        for (int it = 0; it < 8; it++) {
            int idx = tid + it * 256;
            int d = idx & 15, nn = idx >> 4;
            ks[nn][d] = kb[(size_t)n0 * 16 + idx];
            vs[nn][d] = vb[(size_t)n0 * 16 + idx];
        }
        __syncthreads();
#pragma unroll
        for (int nn = 0; nn < 128; nn++) acc += ks[nn][x] * vs[nn][y];
        __syncthreads();
    }
    KV[((size_t)b * HLt + hl) * 256 + tid] = acc;
}

// x5[b][h*16+y][n][l] = sum_x QS[b,h,l,n,x]*kv[b,h,l,x,y] + VT[b,h,l,n,y]
__global__ __launch_bounds__(384) void attn_kernel(
    const float* __restrict__ QS, const float* __restrict__ VT,
    const float* __restrict__ KV, float* __restrict__ XO)
{
    const int n0 = blockIdx.x * 32, h = blockIdx.y, b = blockIdx.z;
    __shared__ float kvs[16 * 16 * Ll];   // [x][y][l]
    const int tid = threadIdx.x;
    for (int idx = tid; idx < 16 * 16 * Ll; idx += 384) {
        const int l = idx % Ll, xy = idx / Ll;
        kvs[idx] = KV[((size_t)b * HLt + h * Ll + l) * 256 + xy];
    }
    __syncthreads();
    const int nloc = tid / Ll, l = tid % Ll;
    const int n = n0 + nloc;
    const float* qp = &QS[(((size_t)(b * Hh + h) * Ll + l) * Nn + n) * 16];
    const float* vp = &VT[(((size_t)(b * Hh + h) * Ll + l) * Nn + n) * 16];
    float q[16], o[16];
    *(float4*)&q[0]  = ((const float4*)qp)[0]; *(float4*)&q[4]  = ((const float4*)qp)[1];
    *(float4*)&q[8]  = ((const float4*)qp)[2]; *(float4*)&q[12] = ((const float4*)qp)[3];
    *(float4*)&o[0]  = ((const float4*)vp)[0]; *(float4*)&o[4]  = ((const float4*)vp)[1];
    *(float4*)&o[8]  = ((const float4*)vp)[2]; *(float4*)&o[12] = ((const float4*)vp)[3];
#pragma unroll
    for (int x = 0; x < 16; x++) {
        const float qx = q[x];
#pragma unroll
        for (int y = 0; y < 16; y++) o[y] += qx * kvs[(x * 16 + y) * Ll + l];
    }
    float* xb = XO + (size_t)b * Cc * NL;
#pragma unroll
    for (int y = 0; y < 16; y++)
        xb[(size_t)(h * 16 + y) * NL + n * Ll + l] = o[y];
}

// out_x = (Y*gate) * (weight+1) + bias
__global__ __launch_bounds__(256) void final_kernel(
    const float* __restrict__ Y, const float* __restrict__ gate,
    const float* __restrict__ wgt, const float* __restrict__ bias,
    float* __restrict__ OX)
{
    const size_t i4 = (size_t)blockIdx.x * 256 + threadIdx.x;
    if (i4 >= X_SZ / 4) return;
    const size_t rest4 = i4 % (Cc * NL / 4);
    const int b = (int)(i4 / (Cc * NL / 4));
    const int c = (int)(rest4 / (NL / 4));
    const float g = gate[b * Cc + c];
    float4 y = ((const float4*)Y)[i4];
    float4 w = ((const float4*)wgt)[rest4];
    float4 bi = ((const float4*)bias)[rest4];
    float4 r;
    r.x = y.x * g * (w.x + 1.f) + bi.x;
    r.y = y.y * g * (w.y + 1.f) + bi.y;
    r.z = y.z * g * (w.z + 1.f) + bi.z;
    r.w = y.w * g * (w.w + 1.f) + bi.w;
    ((float4*)OX)[i4] = r;
}

// A_f = A_h + A_p (broadcast over b)
__global__ __launch_bounds__(256) void af_kernel(float* __restrict__ out)
{
    const size_t i = (size_t)blockIdx.x * 256 + threadIdx.x;
    const float4* ah = (const float4*)(out + AH_OFF);
    const float4* ap = (const float4*)(out + AP_OFF);
    float4* af = (float4*)(out + AF_OFF);
    float4 a = ah[i];
    float4 p = ap[i & (AP_SZ / 4 - 1)];
    float4 r = {a.x + p.x, a.y + p.y, a.z + p.z, a.w + p.w};
    af[i] = r;
}

// =====================================================================
extern "C" void kernel_launch(void* const* d_in, const int* in_sizes, int n_in,
                              void* d_out, int out_size)
{
    (void)in_sizes; (void)n_in; (void)out_size;
    const float* x    = (const float*)d_in[0];
    const float* Wq   = (const float*)d_in[1];
    const float* bq   = (const float*)d_in[2];
    const float* fq1  = (const float*)d_in[3];
    const float* fq2  = (const float*)d_in[4];
    const float* Wv   = (const float*)d_in[5];
    const float* bv   = (const float*)d_in[6];
    const float* fv1  = (const float*)d_in[7];
    const float* fv2  = (const float*)d_in[8];
    const float* Wc   = (const float*)d_in[9];
    const float* bc   = (const float*)d_in[10];
    const float* fc1  = (const float*)d_in[11];
    const float* fc2  = (const float*)d_in[12];
    const float* mem  = (const float*)d_in[13];
    const float* wgt  = (const float*)d_in[14];
    const float* bia  = (const float*)d_in[15];
    const float* nv1  = (const float*)d_in[16];
    const float* nv2  = (const float*)d_in[17];
    float* out = (float*)d_out;

    float *SA, *SB, *SC, *GK, *GKV, *GATE, *GPS;
    __nv_bfloat16 *QH, *KH;
    cudaGetSymbolAddress((void**)&SA,   g_SA);
    cudaGetSymbolAddress((void**)&SB,   g_SB);
    cudaGetSymbolAddress((void**)&SC,   g_SC);
    cudaGetSymbolAddress((void**)&GK,   g_K);
    cudaGetSymbolAddress((void**)&GKV,  g_KV);
    cudaGetSymbolAddress((void**)&GATE, g_gate);
    cudaGetSymbolAddress((void**)&GPS,  g_psum);
    cudaGetSymbolAddress((void**)&QH,   g_Qh);
    cudaGetSymbolAddress((void**)&KH,   g_Kh);
    float* gate_q = GATE;
    float* gate_v = GATE + Bb * Cc;
    float* gate_c = GATE + 2 * Bb * Cc;
    float* ps_q = GPS;
    float* ps_v = GPS + Bb * 96 * Cc;
    float* ps_c = GPS + 2 * Bb * 96 * Cc;

    const dim3 convGrid(NL / 128, Bb);

    // q and v conv branches (pool fused)
    conv_relu_kernel<<<convGrid, 256>>>(x, Wq, bq, SA, ps_q);
    conv_relu_kernel<<<convGrid, 256>>>(x, Wv, bv, SB, ps_v);
    se_kernel<<<Bb, 128>>>(ps_q, fq1, fq2, gate_q);
    se_kernel<<<Bb, 128>>>(ps_v, fv1, fv2, gate_v);

    // qs (softmaxed, transposed, fp32+bf16) and gated v (transposed)
    softmax_q_kernel<<<(Bb * Hh * NL) / 256, 256>>>(SA, gate_q, SC, QH);
    trans_v_kernel<<<(Bb * Hh * NL) / 256, 256>>>(SB, gate_v, SA);

    // k softmax (fp32+bf16) and A_p
    ksoft_kernel<<<(HLt * Nn) / 256, 256>>>(mem, GK, KH);
    ap_kernel<<<Nn, 256>>>(nv1, nv2, out + AP_OFF);

    // A_h via bf16 HMMA tensor cores
    ah_mma_kernel<<<dim3(8, 8, Bb), 256>>>(QH, KH, out + AH_OFF);

    // kv then attention output (attn_dyn == v since A_p rows sum to 1)
    kv_kernel<<<dim3(HLt, Bb), 256>>>(GK, SA, GKV);
    attn_kernel<<<dim3(Nn / 32, Hh, Bb), 384>>>(SC, SA, GKV, SB);

    // output conv branch + SE + final affine
    conv_relu_kernel<<<convGrid, 256>>>(SB, Wc, bc, SC, ps_c);
    se_kernel<<<Bb, 128>>>(ps_c, fc1, fc2, gate_c);
    final_kernel<<<(X_SZ / 4 + 255) / 256, 256>>>(SC, gate_c, wgt, bia, out + X_OFF);

    // passthrough outputs + A_f
    cudaMemcpyAsync(out + W_OFF, wgt, (size_t)WB_SZ * sizeof(float),
                    cudaMemcpyDeviceToDevice, 0);
    cudaMemcpyAsync(out + B_OFF, bia, (size_t)WB_SZ * sizeof(float),
                    cudaMemcpyDeviceToDevice, 0);
    af_kernel<<<AH_SZ / 4 / 256, 256>>>(out);
}

// round 7
// speedup vs baseline: 4.2079x; 1.3555x over previous
#include <cuda_runtime.h>
#include <cuda_bf16.h>
#include <math.h>
#include <stdint.h>

// ---------------- problem constants ----------------
#define Bb   16
#define Cc   128
#define Nn   1024
#define Ll   12
#define Hh   8
#define DKk  16
#define NL   12288          // Nn*Ll
#define HLt  96             // Hh*Ll

#define X_SZ   25165824     // B*C*N*L
#define WB_SZ  1572864      // C*N*L
#define AP_SZ  1048576      // N*N
#define AH_SZ  16777216     // B*N*N

#define X_OFF   0
#define W_OFF   25165824
#define B_OFF   26738688
#define AP_OFF  28311552
#define AH_OFF  29360128
#define AF_OFF  46137344

// ---------------- scratch (static device globals; no allocs) ----------------
__device__ float g_SA[X_SZ];
__device__ float g_SB[X_SZ];
__device__ float g_SC[X_SZ];
__device__ float g_K[HLt * Nn * DKk];            // softmaxed memory (fp32, for kv)
__device__ float g_KV[Bb * HLt * DKk * DKk];     // kv per (b,h,l)
__device__ float g_gate[3 * Bb * Cc];            // SE gates: q, v, c
__device__ float g_psum[3 * Bb * 192 * Cc];      // per-conv-block pool partials
__device__ float g_Wsp[6 * Cc * Cc];             // W tf32 splits: qh,ql,vh,vl,ch,cl
__device__ __nv_bfloat16 g_Qh[(size_t)Bb * HLt * Nn * DKk];  // bf16 qs for MMA
__device__ __nv_bfloat16 g_Kh[HLt * Nn * DKk];               // bf16 k for MMA

// ---------------- tf32 helpers ----------------
__device__ __forceinline__ void tf32_split(float x, float& hi, float& lo) {
    uint32_t hb, lb;
    asm("cvt.rna.tf32.f32 %0, %1;" : "=r"(hb) : "f"(x));
    float hf = __uint_as_float(hb);
    float r = x - hf;
    asm("cvt.rna.tf32.f32 %0, %1;" : "=r"(lb) : "f"(r));
    hi = hf; lo = __uint_as_float(lb);
}

#define MMA_TF32(d, a, b0_, b1_) \
    asm volatile("mma.sync.aligned.m16n8k8.row.col.f32.tf32.tf32.f32 " \
        "{%0,%1,%2,%3}, {%4,%5,%6,%7}, {%8,%9}, {%0,%1,%2,%3};" \
        : "+f"((d)[0]), "+f"((d)[1]), "+f"((d)[2]), "+f"((d)[3]) \
        : "r"((a)[0]), "r"((a)[1]), "r"((a)[2]), "r"((a)[3]), \
          "r"(b0_), "r"(b1_))

// W pre-split: 16384 elements -> hi/lo tf32 pair
__global__ __launch_bounds__(256) void wsplit_kernel(
    const float* __restrict__ W, float* __restrict__ Whi, float* __restrict__ Wlo)
{
    const int i = blockIdx.x * 256 + threadIdx.x;
    float h, l;
    tf32_split(W[i], h, l);
    Whi[i] = h; Wlo[i] = l;
}

// =====================================================================
// 1x1 conv via tf32-split tensor cores (3 MMAs: hh + hl + lh), fp32 accum.
// Y[o][m] = relu(sum_k W[o][k] X[k][m] + bias[o]); pool partials fused.
// 128(o) x 128(m) tile per CTA, 8 warps (4x2), K chunked by 16.
// =====================================================================
#define WST 20      // W smem row stride (floats)
#define BST 136     // X smem row stride (floats)
__global__ __launch_bounds__(256) void conv_tf32_kernel(
    const float* __restrict__ X, const float* __restrict__ Whi,
    const float* __restrict__ Wlo, const float* __restrict__ bias,
    float* __restrict__ Y, float* __restrict__ psum)
{
    __shared__ float WsH[128 * WST], WsL[128 * WST];
    __shared__ float BsH[16 * BST],  BsL[16 * BST];
    const int b = blockIdx.y, mblk = blockIdx.x, m0 = mblk * 128;
    const int tid = threadIdx.x, wid = tid >> 5, lane = tid & 31;
    const int wm = wid & 3, wn = wid >> 2, gi = lane >> 2, tig = lane & 3;

    float c[2][8][4];
#pragma unroll
    for (int mi = 0; mi < 2; mi++)
#pragma unroll
        for (int ni = 0; ni < 8; ni++)
#pragma unroll
            for (int q = 0; q < 4; q++) c[mi][ni][q] = 0.f;

    const float* Xb = X + (size_t)b * Cc * NL;

    for (int k0 = 0; k0 < Cc; k0 += 16) {
        __syncthreads();
#pragma unroll
        for (int it = 0; it < 2; it++) {        // W chunk: 128 x 16
            const int idx = tid + it * 256;     // float4 units
            const int o = idx >> 2, kq = idx & 3;
            float4 h = *(const float4*)&Whi[o * Cc + k0 + kq * 4];
            float4 l = *(const float4*)&Wlo[o * Cc + k0 + kq * 4];
            *(float4*)&WsH[o * WST + kq * 4] = h;
            *(float4*)&WsL[o * WST + kq * 4] = l;
        }
#pragma unroll
        for (int it = 0; it < 2; it++) {        // X chunk: 16 x 128, split
            const int idx = tid + it * 256;
            const int k = idx >> 5, mq = idx & 31;
            float4 v = *(const float4*)&Xb[(size_t)(k0 + k) * NL + m0 + mq * 4];
            float4 hv, lv;
            tf32_split(v.x, hv.x, lv.x);
            tf32_split(v.y, hv.y, lv.y);
            tf32_split(v.z, hv.z, lv.z);
            tf32_split(v.w, hv.w, lv.w);
            *(float4*)&BsH[k * BST + mq * 4] = hv;
            *(float4*)&BsL[k * BST + mq * 4] = lv;
        }
        __syncthreads();
#pragma unroll
        for (int ks = 0; ks < 16; ks += 8) {
            uint32_t aH[2][4], aL[2][4];
#pragma unroll
            for (int mi = 0; mi < 2; mi++) {
                const int r = (wm * 32 + mi * 16 + gi) * WST + ks + tig;
                aH[mi][0] = __float_as_uint(WsH[r]);
                aH[mi][1] = __float_as_uint(WsH[r + 8 * WST]);
                aH[mi][2] = __float_as_uint(WsH[r + 4]);
                aH[mi][3] = __float_as_uint(WsH[r + 8 * WST + 4]);
                aL[mi][0] = __float_as_uint(WsL[r]);
                aL[mi][1] = __float_as_uint(WsL[r + 8 * WST]);
                aL[mi][2] = __float_as_uint(WsL[r + 4]);
                aL[mi][3] = __float_as_uint(WsL[r + 8 * WST + 4]);
            }
#pragma unroll
            for (int ni = 0; ni < 8; ni++) {
                const int base = (ks + tig) * BST + wn * 64 + ni * 8 + gi;
                const uint32_t bH0 = __float_as_uint(BsH[base]);
                const uint32_t bH1 = __float_as_uint(BsH[base + 4 * BST]);
                const uint32_t bL0 = __float_as_uint(BsL[base]);
                const uint32_t bL1 = __float_as_uint(BsL[base + 4 * BST]);
#pragma unroll
                for (int mi = 0; mi < 2; mi++) {
                    MMA_TF32(c[mi][ni], aH[mi], bH0, bH1);
                    MMA_TF32(c[mi][ni], aH[mi], bL0, bL1);
                    MMA_TF32(c[mi][ni], aL[mi], bH0, bH1);
                }
            }
        }
    }

    float* Yb = Y + (size_t)b * Cc * NL;
    float rs[2][2] = {{0.f, 0.f}, {0.f, 0.f}};
#pragma unroll
    for (int mi = 0; mi < 2; mi++) {
        const int o0 = wm * 32 + mi * 16 + gi, o1 = o0 + 8;
        const float b0v = bias[o0], b1v = bias[o1];
#pragma unroll
        for (int ni = 0; ni < 8; ni++) {
            const int m = m0 + wn * 64 + ni * 8 + tig * 2;
            float v0 = fmaxf(c[mi][ni][0] + b0v, 0.f);
            float v1 = fmaxf(c[mi][ni][1] + b0v, 0.f);
            float v2 = fmaxf(c[mi][ni][2] + b1v, 0.f);
            float v3 = fmaxf(c[mi][ni][3] + b1v, 0.f);
            float2 w0 = {v0, v1}, w1 = {v2, v3};
            *(float2*)&Yb[(size_t)o0 * NL + m] = w0;
            *(float2*)&Yb[(size_t)o1 * NL + m] = w1;
            rs[mi][0] += v0 + v1; rs[mi][1] += v2 + v3;
        }
    }
#pragma unroll
    for (int mi = 0; mi < 2; mi++)
#pragma unroll
        for (int hh = 0; hh < 2; hh++) {
            float s = rs[mi][hh];
            s += __shfl_down_sync(0xffffffffu, s, 2);
            s += __shfl_down_sync(0xffffffffu, s, 1);
            rs[mi][hh] = s;
        }
    if (tig == 0) {
        float* pp = psum + ((size_t)(b * 96 + mblk) * 2 + wn) * Cc;
        pp[wm * 32 + gi]      = rs[0][0];
        pp[wm * 32 + gi + 8]  = rs[0][1];
        pp[wm * 32 + 16 + gi]     = rs[1][0];
        pp[wm * 32 + 16 + gi + 8] = rs[1][1];
    }
}

// tiny SE: reduce 192 partials per (b,c), MLP, sigmoid gate
__global__ __launch_bounds__(128) void se_kernel(
    const float* __restrict__ psum, const float* __restrict__ f1,
    const float* __restrict__ f2, float* __restrict__ gate)
{
    __shared__ float means[Cc];
    __shared__ float h1[8];
    const int b = blockIdx.x, tid = threadIdx.x;
    float s = 0.f;
    for (int m = 0; m < 192; m++)
        s += psum[((size_t)(b * 192 + m)) * Cc + tid];
    means[tid] = s * (1.f / (float)NL);
    __syncthreads();
    if (tid < 8) {
        float t = 0.f;
        for (int c = 0; c < Cc; c++) t += f1[tid * Cc + c] * means[c];
        h1[tid] = t > 0.f ? t : 0.f;
    }
    __syncthreads();
    float t = 0.f;
#pragma unroll
    for (int j = 0; j < 8; j++) t += f2[tid * 8 + j] * h1[j];
    gate[b * Cc + tid] = 1.f / (1.f + expf(-t));
}

// =====================================================================
// q branch: gate, *scale, softmax over DK, transpose -> fp32 QS + bf16 QSh
// =====================================================================
__global__ __launch_bounds__(256) void softmax_q_kernel(
    const float* __restrict__ Y, const float* __restrict__ gate,
    float* __restrict__ QS, __nv_bfloat16* __restrict__ QSh)
{
    const int t = blockIdx.x * 256 + threadIdx.x;
    const int nl = t % NL;
    const int bh = t / NL;
    const int h = bh & 7, b = bh >> 3;
    const int n = nl / Ll, l = nl % Ll;
    const float scale = 0.25f;

    float v[16]; float mx = -1e30f;
#pragma unroll
    for (int d = 0; d < 16; d++) {
        const int c = h * 16 + d;
        float val = Y[((size_t)b * Cc + c) * NL + nl] * gate[b * Cc + c] * scale;
        v[d] = val; mx = fmaxf(mx, val);
    }
    float s = 0.f;
#pragma unroll
    for (int d = 0; d < 16; d++) { v[d] = expf(v[d] - mx); s += v[d]; }
    const float inv = 1.f / s;
#pragma unroll
    for (int d = 0; d < 16; d++) v[d] *= inv;
    const size_t base = (((size_t)(b * Hh + h) * Ll + l) * Nn + n) * 16;
    float4* out = (float4*)&QS[base];
    out[0] = *(float4*)&v[0];  out[1] = *(float4*)&v[4];
    out[2] = *(float4*)&v[8];  out[3] = *(float4*)&v[12];
    __nv_bfloat162 hb[8];
#pragma unroll
    for (int d = 0; d < 8; d++) hb[d] = __floats2bfloat162_rn(v[2*d], v[2*d+1]);
    uint4* outh = (uint4*)&QSh[base];
    outh[0] = *(uint4*)&hb[0];
    outh[1] = *(uint4*)&hb[4];
}

// v branch: gate + transpose to [B,H,L,N,DK]
__global__ __launch_bounds__(256) void trans_v_kernel(
    const float* __restrict__ Y, const float* __restrict__ gate,
    float* __restrict__ VT)
{
    const int t = blockIdx.x * 256 + threadIdx.x;
    const int nl = t % NL;
    const int bh = t / NL;
    const int h = bh & 7, b = bh >> 3;
    const int n = nl / Ll, l = nl % Ll;

    float v[16];
#pragma unroll
    for (int d = 0; d < 16; d++) {
        const int c = h * 16 + d;
        v[d] = Y[((size_t)b * Cc + c) * NL + nl] * gate[b * Cc + c];
    }
    float4* out = (float4*)&VT[(((size_t)(b * Hh + h) * Ll + l) * Nn + n) * 16];
    out[0] = *(float4*)&v[0];  out[1] = *(float4*)&v[4];
    out[2] = *(float4*)&v[8];  out[3] = *(float4*)&v[12];
}

// k = softmax(memory * scale, axis=-1) -> fp32 + bf16
__global__ __launch_bounds__(256) void ksoft_kernel(
    const float* __restrict__ mem, float* __restrict__ K,
    __nv_bfloat16* __restrict__ Kh)
{
    const int t = blockIdx.x * 256 + threadIdx.x;
    const float scale = 0.25f;
    float v[16]; float mx = -1e30f;
    const float4* p = (const float4*)(mem + (size_t)t * 16);
    float4 r[4] = {p[0], p[1], p[2], p[3]};
#pragma unroll
    for (int q = 0; q < 4; q++) {
        v[q*4+0] = r[q].x * scale; v[q*4+1] = r[q].y * scale;
        v[q*4+2] = r[q].z * scale; v[q*4+3] = r[q].w * scale;
    }
#pragma unroll
    for (int d = 0; d < 16; d++) mx = fmaxf(mx, v[d]);
    float s = 0.f;
#pragma unroll
    for (int d = 0; d < 16; d++) { v[d] = expf(v[d] - mx); s += v[d]; }
    const float inv = 1.f / s;
#pragma unroll
    for (int d = 0; d < 16; d++) v[d] *= inv;
    float4* out = (float4*)(K + (size_t)t * 16);
    out[0] = *(float4*)&v[0];  out[1] = *(float4*)&v[4];
    out[2] = *(float4*)&v[8];  out[3] = *(float4*)&v[12];
    __nv_bfloat162 hb[8];
#pragma unroll
    for (int d = 0; d < 8; d++) hb[d] = __floats2bfloat162_rn(v[2*d], v[2*d+1]);
    uint4* outh = (uint4*)&Kh[(size_t)t * 16];
    outh[0] = *(uint4*)&hb[0];
    outh[1] = *(uint4*)&hb[4];
}

// A_p = softmax(relu(nv1 @ nv2), axis=-1), one block per row n
__global__ __launch_bounds__(256) void ap_kernel(
    const float* __restrict__ nv1, const float* __restrict__ nv2,
    float* __restrict__ AP)
{
    const int n = blockIdx.x, tid = threadIdx.x, lane = tid & 31, wid = tid >> 5;
    __shared__ float red[8];
    __shared__ float bval;
    float a[10];
#pragma unroll
    for (int t = 0; t < 10; t++) a[t] = nv1[n * 10 + t];
    float v[4];
#pragma unroll
    for (int j = 0; j < 4; j++) {
        const int m = tid + j * 256;
        float s = 0.f;
#pragma unroll
        for (int t = 0; t < 10; t++) s += a[t] * nv2[t * Nn + m];
        v[j] = s > 0.f ? s : 0.f;
    }
    float mx = fmaxf(fmaxf(v[0], v[1]), fmaxf(v[2], v[3]));
#pragma unroll
    for (int o = 16; o > 0; o >>= 1) mx = fmaxf(mx, __shfl_xor_sync(0xffffffffu, mx, o));
    if (lane == 0) red[wid] = mx;
    __syncthreads();
    if (tid == 0) { float t = red[0]; for (int w = 1; w < 8; w++) t = fmaxf(t, red[w]); bval = t; }
    __syncthreads();
    mx = bval;
    float s = 0.f;
#pragma unroll
    for (int j = 0; j < 4; j++) { v[j] = expf(v[j] - mx); s += v[j]; }
#pragma unroll
    for (int o = 16; o > 0; o >>= 1) s += __shfl_xor_sync(0xffffffffu, s, o);
    if (lane == 0) red[wid] = s;
    __syncthreads();
    if (tid == 0) { float t = 0.f; for (int w = 0; w < 8; w++) t += red[w]; bval = t; }
    __syncthreads();
    const float inv = 1.f / bval;
#pragma unroll
    for (int j = 0; j < 4; j++) AP[(size_t)n * Nn + tid + j * 256] = v[j] * inv;
}

// =====================================================================
// A_h via bf16 HMMA; epilogue also emits A_f = A_h + A_p.
// =====================================================================
#define BKP 40
__global__ __launch_bounds__(256) void ah_mma_kernel(
    const __nv_bfloat16* __restrict__ Qh, const __nv_bfloat16* __restrict__ Kh,
    float* __restrict__ AH, const float* __restrict__ AP,
    float* __restrict__ AF)
{
    __shared__ __nv_bfloat16 As[128 * BKP];
    __shared__ __nv_bfloat16 Bs[128 * BKP];
    const int b  = blockIdx.z;
    const int n0 = blockIdx.y * 128;
    const int m0 = blockIdx.x * 128;
    const int tid = threadIdx.x, wid = tid >> 5, lane = tid & 31;
    const int wm = wid & 3, wn = wid >> 2;
    const int gi = lane >> 2, tig = lane & 3;

    float c[2][8][4];
#pragma unroll
    for (int mi = 0; mi < 2; mi++)
#pragma unroll
        for (int ni = 0; ni < 8; ni++)
#pragma unroll
            for (int q = 0; q < 4; q++) c[mi][ni][q] = 0.f;

    const __nv_bfloat16* Qb = Qh + (size_t)b * HLt * Nn * DKk;
    const int lr = tid & 127;
    const int ls = tid >> 7;

    for (int kc = 0; kc < 48; kc++) {
        const int hl0 = kc * 2;
        __syncthreads();
        {
            const size_t gofs = ((size_t)(hl0 + ls) * Nn) * 16;
            const uint4* ga = (const uint4*)(Qb + gofs + (size_t)(n0 + lr) * 16);
            const uint4* gb = (const uint4*)(Kh + gofs + (size_t)(m0 + lr) * 16);
            uint4 a0 = ga[0], a1 = ga[1];
            uint4 b0 = gb[0], b1 = gb[1];
            __nv_bfloat16* pa = As + lr * BKP + ls * 16;
            __nv_bfloat16* pb = Bs + lr * BKP + ls * 16;
            *(uint4*)pa = a0; *(uint4*)(pa + 8) = a1;
            *(uint4*)pb = b0; *(uint4*)(pb + 8) = b1;
        }
        __syncthreads();
#pragma unroll
        for (int ks = 0; ks < 32; ks += 16) {
            uint32_t a[2][4];
#pragma unroll
            for (int mi = 0; mi < 2; mi++) {
                const __nv_bfloat16* ap =
                    As + (wm * 32 + mi * 16 + gi) * BKP + ks + tig * 2;
                a[mi][0] = *(const uint32_t*)ap;
                a[mi][1] = *(const uint32_t*)(ap + 8 * BKP);
                a[mi][2] = *(const uint32_t*)(ap + 8);
                a[mi][3] = *(const uint32_t*)(ap + 8 * BKP + 8);
            }
#pragma unroll
            for (int ni = 0; ni < 8; ni++) {
                const __nv_bfloat16* bp =
                    Bs + (wn * 64 + ni * 8 + gi) * BKP + ks + tig * 2;
                const uint32_t b0 = *(const uint32_t*)bp;
                const uint32_t b1 = *(const uint32_t*)(bp + 8);
#pragma unroll
                for (int mi = 0; mi < 2; mi++) {
                    asm volatile(
                        "mma.sync.aligned.m16n8k16.row.col.f32.bf16.bf16.f32 "
                        "{%0,%1,%2,%3}, {%4,%5,%6,%7}, {%8,%9}, {%0,%1,%2,%3};"
                        : "+f"(c[mi][ni][0]), "+f"(c[mi][ni][1]),
                          "+f"(c[mi][ni][2]), "+f"(c[mi][ni][3])
                        : "r"(a[mi][0]), "r"(a[mi][1]),
                          "r"(a[mi][2]), "r"(a[mi][3]),
                          "r"(b0), "r"(b1));
                }
            }
        }
    }

    float* Ab = AH + (size_t)b * Nn * Nn;
    float* Fb = AF + (size_t)b * Nn * Nn;
#pragma unroll
    for (int mi = 0; mi < 2; mi++) {
        const int r0 = n0 + wm * 32 + mi * 16 + gi;
#pragma unroll
        for (int ni = 0; ni < 8; ni++) {
            const int col = m0 + wn * 64 + ni * 8 + tig * 2;
            float2 v0 = {c[mi][ni][0] * 0.125f, c[mi][ni][1] * 0.125f};
            float2 v1 = {c[mi][ni][2] * 0.125f, c[mi][ni][3] * 0.125f};
            float2 p0 = *(const float2*)&AP[(size_t)r0 * Nn + col];
            float2 p1 = *(const float2*)&AP[(size_t)(r0 + 8) * Nn + col];
            *(float2*)&Ab[(size_t)r0 * Nn + col] = v0;
            *(float2*)&Ab[(size_t)(r0 + 8) * Nn + col] = v1;
            float2 f0 = {v0.x + p0.x, v0.y + p0.y};
            float2 f1 = {v1.x + p1.x, v1.y + p1.y};
            *(float2*)&Fb[(size_t)r0 * Nn + col] = f0;
            *(float2*)&Fb[(size_t)(r0 + 8) * Nn + col] = f1;
        }
    }
}

// kv[b][hl][x][y] = sum_n K[hl][n][x] * VT[b][hl][n][y]
__global__ __launch_bounds__(256) void kv_kernel(
    const float* __restrict__ K, const float* __restrict__ VT,
    float* __restrict__ KV)
{
    const int hl = blockIdx.x, b = blockIdx.y;
    __shared__ float ks[128][16];
    __shared__ float vs[128][16];
    const int tid = threadIdx.x;
    const int x = tid >> 4, y = tid & 15;
    float acc = 0.f;
    const float* kb = K  + (size_t)hl * Nn * 16;
    const float* vb = VT + ((size_t)b * HLt + hl) * Nn * 16;
    for (int n0 = 0; n0 < Nn; n0 += 128) {
#pragma unroll
        for (int it = 0; it < 8; it++) {
            int idx = tid + it * 256;
            int d = idx & 15, nn = idx >> 4;
            ks[nn][d] = kb[(size_t)n0 * 16 + idx];
            vs[nn][d] = vb[(size_t)n0 * 16 + idx];
        }
        __syncthreads();
#pragma unroll
        for (int nn = 0; nn < 128; nn++) acc += ks[nn][x] * vs[nn][y];
        __syncthreads();
    }
    KV[((size_t)b * HLt + hl) * 256 + tid] = acc;
}

// x5[b][h*16+y][n][l] = sum_x QS[b,h,l,n,x]*kv[b,h,l,x,y] + VT[b,h,l,n,y]
__global__ __launch_bounds__(384) void attn_kernel(
    const float* __restrict__ QS, const float* __restrict__ VT,
    const float* __restrict__ KV, float* __restrict__ XO)
{
    const int n0 = blockIdx.x * 32, h = blockIdx.y, b = blockIdx.z;
    __shared__ float kvs[16 * 16 * Ll];   // [x][y][l]
    const int tid = threadIdx.x;
    for (int idx = tid; idx < 16 * 16 * Ll; idx += 384) {
        const int l = idx % Ll, xy = idx / Ll;
        kvs[idx] = KV[((size_t)b * HLt + h * Ll + l) * 256 + xy];
    }
    __syncthreads();
    const int nloc = tid / Ll, l = tid % Ll;
    const int n = n0 + nloc;
    const float* qp = &QS[(((size_t)(b * Hh + h) * Ll + l) * Nn + n) * 16];
    const float* vp = &VT[(((size_t)(b * Hh + h) * Ll + l) * Nn + n) * 16];
    float q[16], o[16];
    *(float4*)&q[0]  = ((const float4*)qp)[0]; *(float4*)&q[4]  = ((const float4*)qp)[1];
    *(float4*)&q[8]  = ((const float4*)qp)[2]; *(float4*)&q[12] = ((const float4*)qp)[3];
    *(float4*)&o[0]  = ((const float4*)vp)[0]; *(float4*)&o[4]  = ((const float4*)vp)[1];
    *(float4*)&o[8]  = ((const float4*)vp)[2]; *(float4*)&o[12] = ((const float4*)vp)[3];
#pragma unroll
    for (int x = 0; x < 16; x++) {
        const float qx = q[x];
#pragma unroll
        for (int y = 0; y < 16; y++) o[y] += qx * kvs[(x * 16 + y) * Ll + l];
    }
    float* xb = XO + (size_t)b * Cc * NL;
#pragma unroll
    for (int y = 0; y < 16; y++)
        xb[(size_t)(h * 16 + y) * NL + n * Ll + l] = o[y];
}

// out_x = (Y*gate) * (weight+1) + bias
__global__ __launch_bounds__(256) void final_kernel(
    const float* __restrict__ Y, const float* __restrict__ gate,
    const float* __restrict__ wgt, const float* __restrict__ bias,
    float* __restrict__ OX)
{
    const size_t i4 = (size_t)blockIdx.x * 256 + threadIdx.x;
    if (i4 >= X_SZ / 4) return;
    const size_t rest4 = i4 % (Cc * NL / 4);
    const int b = (int)(i4 / (Cc * NL / 4));
    const int c = (int)(rest4 / (NL / 4));
    const float g = gate[b * Cc + c];
    float4 y = ((const float4*)Y)[i4];
    float4 w = ((const float4*)wgt)[rest4];
    float4 bi = ((const float4*)bias)[rest4];
    float4 r;
    r.x = y.x * g * (w.x + 1.f) + bi.x;
    r.y = y.y * g * (w.y + 1.f) + bi.y;
    r.z = y.z * g * (w.z + 1.f) + bi.z;
    r.w = y.w * g * (w.w + 1.f) + bi.w;
    ((float4*)OX)[i4] = r;
}

// =====================================================================
extern "C" void kernel_launch(void* const* d_in, const int* in_sizes, int n_in,
                              void* d_out, int out_size)
{
    (void)in_sizes; (void)n_in; (void)out_size;
    const float* x    = (const float*)d_in[0];
    const float* Wq   = (const float*)d_in[1];
    const float* bq   = (const float*)d_in[2];
    const float* fq1  = (const float*)d_in[3];
    const float* fq2  = (const float*)d_in[4];
    const float* Wv   = (const float*)d_in[5];
    const float* bv   = (const float*)d_in[6];
    const float* fv1  = (const float*)d_in[7];
    const float* fv2  = (const float*)d_in[8];
    const float* Wc   = (const float*)d_in[9];
    const float* bc   = (const float*)d_in[10];
    const float* fc1  = (const float*)d_in[11];
    const float* fc2  = (const float*)d_in[12];
    const float* mem  = (const float*)d_in[13];
    const float* wgt  = (const float*)d_in[14];
    const float* bia  = (const float*)d_in[15];
    const float* nv1  = (const float*)d_in[16];
    const float* nv2  = (const float*)d_in[17];
    float* out = (float*)d_out;

    float *SA, *SB, *SC, *GK, *GKV, *GATE, *GPS, *GWS;
    __nv_bfloat16 *QH, *KH;
    cudaGetSymbolAddress((void**)&SA,   g_SA);
    cudaGetSymbolAddress((void**)&SB,   g_SB);
    cudaGetSymbolAddress((void**)&SC,   g_SC);
    cudaGetSymbolAddress((void**)&GK,   g_K);
    cudaGetSymbolAddress((void**)&GKV,  g_KV);
    cudaGetSymbolAddress((void**)&GATE, g_gate);
    cudaGetSymbolAddress((void**)&GPS,  g_psum);
    cudaGetSymbolAddress((void**)&GWS,  g_Wsp);
    cudaGetSymbolAddress((void**)&QH,   g_Qh);
    cudaGetSymbolAddress((void**)&KH,   g_Kh);
    float* gate_q = GATE;
    float* gate_v = GATE + Bb * Cc;
    float* gate_c = GATE + 2 * Bb * Cc;
    float* ps_q = GPS;
    float* ps_v = GPS + (size_t)Bb * 192 * Cc;
    float* ps_c = GPS + (size_t)2 * Bb * 192 * Cc;
    float* Wqh = GWS;                 float* Wql = GWS + Cc * Cc;
    float* Wvh = GWS + 2 * Cc * Cc;   float* Wvl = GWS + 3 * Cc * Cc;
    float* Wch = GWS + 4 * Cc * Cc;   float* Wcl = GWS + 5 * Cc * Cc;

    // pre-split all three conv weights into tf32 hi/lo
    wsplit_kernel<<<Cc * Cc / 256, 256>>>(Wq, Wqh, Wql);
    wsplit_kernel<<<Cc * Cc / 256, 256>>>(Wv, Wvh, Wvl);
    wsplit_kernel<<<Cc * Cc / 256, 256>>>(Wc, Wch, Wcl);

    const dim3 convGrid(NL / 128, Bb);

    // q and v conv branches (tensor-core tf32-split, pool fused)
    conv_tf32_kernel<<<convGrid, 256>>>(x, Wqh, Wql, bq, SA, ps_q);
    conv_tf32_kernel<<<convGrid, 256>>>(x, Wvh, Wvl, bv, SB, ps_v);
    se_kernel<<<Bb, 128>>>(ps_q, fq1, fq2, gate_q);
    se_kernel<<<Bb, 128>>>(ps_v, fv1, fv2, gate_v);

    // qs (softmaxed, transposed, fp32+bf16) and gated v (transposed)
    softmax_q_kernel<<<(Bb * Hh * NL) / 256, 256>>>(SA, gate_q, SC, QH);
    trans_v_kernel<<<(Bb * Hh * NL) / 256, 256>>>(SB, gate_v, SA);

    // k softmax (fp32+bf16) and A_p
    ksoft_kernel<<<(HLt * Nn) / 256, 256>>>(mem, GK, KH);
    ap_kernel<<<Nn, 256>>>(nv1, nv2, out + AP_OFF);

    // A_h via bf16 HMMA (A_f fused into epilogue)
    ah_mma_kernel<<<dim3(8, 8, Bb), 256>>>(QH, KH, out + AH_OFF,
                                           out + AP_OFF, out + AF_OFF);

    // kv then attention output (attn_dyn == v since A_p rows sum to 1)
    kv_kernel<<<dim3(HLt, Bb), 256>>>(GK, SA, GKV);
    attn_kernel<<<dim3(Nn / 32, Hh, Bb), 384>>>(SC, SA, GKV, SB);

    // output conv branch + SE + final affine
    conv_tf32_kernel<<<convGrid, 256>>>(SB, Wch, Wcl, bc, SC, ps_c);
    se_kernel<<<Bb, 128>>>(ps_c, fc1, fc2, gate_c);
    final_kernel<<<(X_SZ / 4 + 255) / 256, 256>>>(SC, gate_c, wgt, bia, out + X_OFF);

    // passthrough outputs
    cudaMemcpyAsync(out + W_OFF, wgt, (size_t)WB_SZ * sizeof(float),
                    cudaMemcpyDeviceToDevice, 0);
    cudaMemcpyAsync(out + B_OFF, bia, (size_t)WB_SZ * sizeof(float),
                    cudaMemcpyDeviceToDevice, 0);
}